// round 2
// baseline (speedup 1.0000x reference)
#include <cuda_runtime.h>
#include <cuda_bf16.h>
#include <cstdint>

// ---------------------------------------------------------------------------
// DMTet geometry, fully on-device. Outputs concatenated into d_out (float32):
//   [ verts (E*3) | faces (Fc*3) | verts_tetmesh (U*3) | tets_tetmesh (T*4) ]
// ---------------------------------------------------------------------------

#define MAXN 400000
#define MAXF 2000000
#define MAXS (6 * MAXF)            // max edge slots (6 per valid tet)
#define MAXTE (12 * MAXF)          // max all_tets entries (4 * 3F rows)
#define PRESCAP (MAXN + MAXS)      // presence domain [0, N+E)
#define NBLK_MAX ((PRESCAP + 2047) / 2048 + 2)

// ---- lookup tables ----
__device__ const int c_NTRI[16]  = {0,1,1,2,1,2,2,1,1,2,2,1,2,1,1,0};
__device__ const int c_NTET[16]  = {0,1,1,3,1,3,3,3,1,3,3,3,3,3,3,1};
__device__ const int c_BE[12]    = {0,1,0,2,0,3,1,2,1,3,2,3};
__device__ const int c_TRI[16][6] = {
    {-1,-1,-1,-1,-1,-1},{1,0,2,-1,-1,-1},{4,0,3,-1,-1,-1},{1,4,2,1,3,4},
    {3,1,5,-1,-1,-1},{2,3,0,2,5,3},{1,4,0,1,5,4},{4,2,5,-1,-1,-1},
    {4,5,2,-1,-1,-1},{4,1,0,4,5,1},{3,2,0,3,5,2},{1,3,5,-1,-1,-1},
    {4,1,2,4,3,1},{3,0,4,-1,-1,-1},{2,0,1,-1,-1,-1},{-1,-1,-1,-1,-1,-1}};
__device__ const int c_TET[16][12] = {
    {-1,-1,-1,-1,-1,-1,-1,-1,-1,-1,-1,-1},{0,4,5,6,-1,-1,-1,-1,-1,-1,-1,-1},
    {1,4,8,7,-1,-1,-1,-1,-1,-1,-1,-1},{7,1,8,6,5,1,7,6,5,0,1,6},
    {2,5,7,9,-1,-1,-1,-1,-1,-1,-1,-1},{4,0,6,7,9,0,7,6,7,0,9,2},
    {4,1,9,8,5,1,9,4,5,1,2,9},{6,0,1,2,8,6,1,2,9,6,8,2},
    {3,6,9,8,-1,-1,-1,-1,-1,-1,-1,-1},{5,0,4,8,5,0,8,3,5,8,9,3},
    {1,4,7,3,4,7,6,3,9,6,7,3},{0,1,5,3,5,1,9,3,5,1,7,9},
    {5,2,3,7,3,6,5,8,3,5,7,8},{0,4,7,8,0,3,8,7,0,3,7,2},
    {4,1,2,3,4,3,2,5,4,3,5,6},{0,1,2,3,-1,-1,-1,-1,-1,-1,-1,-1}};

// ---- scratch (module-static device memory; no runtime allocation) ----
__device__ int g_occ[MAXN];
__device__ int g_ti[MAXF];
__device__ int g_validX[MAXF];
__device__ int g_nt1X[MAXF];
__device__ int g_nt2X[MAXF];
__device__ int g_ntt1X[MAXF];
__device__ int g_ntt3X[MAXF];
__device__ int g_innerX[MAXF];
__device__ int g_bcnt[MAXN];
__device__ int g_bstart[MAXN];
__device__ int g_bcur[MAXN];
__device__ unsigned long long g_bdata[MAXS];
__device__ int g_idxmap[MAXS];
__device__ int g_crossCnt[MAXN];
__device__ int g_crossX[MAXN];
__device__ int g_eA[MAXS];
__device__ int g_eB[MAXS];
__device__ int g_allTets[MAXTE];
__device__ int g_present[PRESCAP];
__device__ int g_presX[PRESCAP];
__device__ int g_bsums[NBLK_MAX];
// meta: 0 validTot 1 nt1Tot 2 nt2Tot 3 ntt1Tot 4 ntt3Tot 5 innerTot
//       6 E  7 U  8 facesOff  9 trows  10 vtOff  11 tetsOff  14 scratch
__device__ int g_meta[16];

// ---------------------------------------------------------------------------
// generic exclusive scan (3 kernels). Values derived from in[] via `mode`.
// ---------------------------------------------------------------------------
__device__ __forceinline__ int scan_val(const int* in, int mode, int i) {
    int t = in[i];
    switch (mode) {
        case -1: return t;
        case 0: return (t != 0 && t != 15) ? 1 : 0;
        case 1: return (t != 0 && t != 15 && c_NTRI[t] == 1) ? 1 : 0;
        case 2: return (t != 0 && t != 15 && c_NTRI[t] == 2) ? 1 : 0;
        case 3: return (t != 0 && t != 15 && c_NTET[t] == 1) ? 1 : 0;
        case 4: return (t != 0 && t != 15 && c_NTET[t] == 3) ? 1 : 0;
        case 5: return (t == 15) ? 1 : 0;
    }
    return 0;
}

__global__ void k_scan_partial(const int* in, int mode, int n, int* bsums) {
    __shared__ int sh[256];
    int b = blockIdx.x, tid = threadIdx.x;
    int base = b * 2048 + tid * 8;
    int s = 0;
#pragma unroll
    for (int j = 0; j < 8; j++) {
        int i = base + j;
        if (i < n) s += scan_val(in, mode, i);
    }
    sh[tid] = s;
    __syncthreads();
    for (int o = 128; o > 0; o >>= 1) {
        if (tid < o) sh[tid] += sh[tid + o];
        __syncthreads();
    }
    if (tid == 0) bsums[b] = sh[0];
}

__global__ void k_scan_single(int* bsums, int nb, int* totalOut) {
    __shared__ int sh[1024];
    int tid = threadIdx.x;
    int carry = 0;
    for (int base = 0; base < nb; base += 1024) {
        int i = base + tid;
        int v = (i < nb) ? bsums[i] : 0;
        sh[tid] = v;
        __syncthreads();
        for (int o = 1; o < 1024; o <<= 1) {
            int t = (tid >= o) ? sh[tid - o] : 0;
            __syncthreads();
            sh[tid] += t;
            __syncthreads();
        }
        if (i < nb) bsums[i] = carry + sh[tid] - v;
        int tot = sh[1023];
        __syncthreads();
        carry += tot;
    }
    if (tid == 0 && totalOut) *totalOut = carry;
}

__global__ void k_scan_final(const int* in, int mode, int n, const int* bsums, int* outp) {
    __shared__ int sh[256];
    int b = blockIdx.x, tid = threadIdx.x;
    int base = b * 2048 + tid * 8;
    int v[8];
    int s = 0;
#pragma unroll
    for (int j = 0; j < 8; j++) {
        int i = base + j;
        v[j] = (i < n) ? scan_val(in, mode, i) : 0;
        s += v[j];
    }
    sh[tid] = s;
    __syncthreads();
    for (int o = 1; o < 256; o <<= 1) {
        int t = (tid >= o) ? sh[tid - o] : 0;
        __syncthreads();
        sh[tid] += t;
        __syncthreads();
    }
    int run = bsums[b] + sh[tid] - s;
#pragma unroll
    for (int j = 0; j < 8; j++) {
        int i = base + j;
        if (i < n) outp[i] = run;
        run += v[j];
    }
}

// ---------------------------------------------------------------------------
// pipeline kernels
// ---------------------------------------------------------------------------
__global__ void k_fill(int* p, int v, int n) {
    int i = blockIdx.x * blockDim.x + threadIdx.x;
    if (i < n) p[i] = v;
}

__global__ void k_occ(const float* sdf, const float* th, int N) {
    int i = blockIdx.x * blockDim.x + threadIdx.x;
    if (i >= N) return;
    float t = th[0];
    float s = sdf[i];
    g_occ[i] = (s > 0.f && s <= t) ? 1 : 0;
}

__global__ void k_ti(const int* tet, int F) {
    int f = blockIdx.x * blockDim.x + threadIdx.x;
    if (f >= F) return;
    int t = 0;
#pragma unroll
    for (int j = 0; j < 4; j++) t |= g_occ[tet[f * 4 + j]] << j;
    g_ti[f] = t;
}

__global__ void k_edge_count(const int* tet, int F) {
    int f = blockIdx.x * blockDim.x + threadIdx.x;
    if (f >= F) return;
    int t = g_ti[f];
    if (t == 0 || t == 15) return;
    int q0 = tet[f * 4 + 0], q1 = tet[f * 4 + 1], q2 = tet[f * 4 + 2], q3 = tet[f * 4 + 3];
    int q[4] = {q0, q1, q2, q3};
#pragma unroll
    for (int k = 0; k < 6; k++) {
        int a = q[c_BE[2 * k]], b = q[c_BE[2 * k + 1]];
        int lo = a < b ? a : b;
        atomicAdd(&g_bcnt[lo], 1);
    }
}

__global__ void k_cur(int N) {
    int i = blockIdx.x * blockDim.x + threadIdx.x;
    if (i < N) g_bcur[i] = g_bstart[i];
}

__global__ void k_edge_scatter(const int* tet, int F) {
    int f = blockIdx.x * blockDim.x + threadIdx.x;
    if (f >= F) return;
    int t = g_ti[f];
    if (t == 0 || t == 15) return;
    int r = g_validX[f];
    int q0 = tet[f * 4 + 0], q1 = tet[f * 4 + 1], q2 = tet[f * 4 + 2], q3 = tet[f * 4 + 3];
    int q[4] = {q0, q1, q2, q3};
#pragma unroll
    for (int k = 0; k < 6; k++) {
        int a = q[c_BE[2 * k]], b = q[c_BE[2 * k + 1]];
        int lo = a < b ? a : b;
        int hi = a < b ? b : a;
        int pos = atomicAdd(&g_bcur[lo], 1);
        g_bdata[pos] = ((unsigned long long)(unsigned)hi << 32) | (unsigned)(r * 6 + k);
    }
}

__global__ void k_bsort(int N) {
    int a = blockIdx.x * blockDim.x + threadIdx.x;
    if (a >= N) return;
    int s = g_bstart[a];
    int n = g_bcnt[a];
    for (int i = 1; i < n; i++) {
        unsigned long long key = g_bdata[s + i];
        int j = i - 1;
        while (j >= 0 && g_bdata[s + j] > key) {
            g_bdata[s + j + 1] = g_bdata[s + j];
            j--;
        }
        g_bdata[s + j + 1] = key;
    }
    int occa = g_occ[a];
    int prev = -1, c = 0;
    for (int i = 0; i < n; i++) {
        int b = (int)(g_bdata[s + i] >> 32);
        if (b != prev) {
            if (occa + g_occ[b] == 1) c++;
            prev = b;
        }
    }
    g_crossCnt[a] = c;
}

__global__ void k_bassign(int N) {
    int a = blockIdx.x * blockDim.x + threadIdx.x;
    if (a >= N) return;
    int s = g_bstart[a];
    int n = g_bcnt[a];
    int base = g_crossX[a];
    int occa = g_occ[a];
    int prev = -1, c = 0, mv = -1;
    for (int i = 0; i < n; i++) {
        unsigned long long d = g_bdata[s + i];
        int b = (int)(d >> 32);
        int slot = (int)(d & 0xffffffffu);
        if (b != prev) {
            if (occa + g_occ[b] == 1) {
                int eid = base + c;
                g_eA[eid] = a;
                g_eB[eid] = b;
                mv = eid;
                c++;
            } else {
                mv = -1;
            }
            prev = b;
        }
        g_idxmap[slot] = mv;
    }
}

__global__ void k_meta1() {
    int E = g_meta[6];
    int Fc = g_meta[1] + 2 * g_meta[2];
    g_meta[8] = 3 * E;
    g_meta[9] = g_meta[3] + 3 * g_meta[4] + g_meta[5];
    g_meta[10] = 3 * E + 3 * Fc;
}

__global__ void k_verts(const float* pos, const float* sdf, const float* th, float* out) {
    int e = blockIdx.x * blockDim.x + threadIdx.x;
    if (e >= g_meta[6]) return;
    int a = g_eA[e], b = g_eB[e];
    float t = th[0];
    float s0 = sdf[a], s1 = sdf[b];
    if (s0 > 0.f && s1 > 0.f) { s0 -= t; s1 -= t; }
    float denom = s0 - s1;
    float w0 = -s1 / denom;
    float w1 = s0 / denom;
#pragma unroll
    for (int c = 0; c < 3; c++)
        out[e * 3 + c] = pos[a * 3 + c] * w0 + pos[b * 3 + c] * w1;
}

__global__ void k_faces(float* out, int F) {
    int f = blockIdx.x * blockDim.x + threadIdx.x;
    if (f >= F) return;
    int t = g_ti[f];
    if (t == 0 || t == 15) return;
    int r = g_validX[f];
    int foff = g_meta[8];
    if (c_NTRI[t] == 1) {
        int row = g_nt1X[f];
#pragma unroll
        for (int j = 0; j < 3; j++)
            out[foff + row * 3 + j] = (float)g_idxmap[r * 6 + c_TRI[t][j]];
    } else {
        int row = g_meta[1] + 2 * g_nt2X[f];
#pragma unroll
        for (int j = 0; j < 6; j++)
            out[foff + row * 3 + j] = (float)g_idxmap[r * 6 + c_TRI[t][j]];
    }
}

__global__ void k_tbuild(const int* tet, int F, int N) {
    int f = blockIdx.x * blockDim.x + threadIdx.x;
    if (f >= F) return;
    int t = g_ti[f];
    if (t == 0) return;
    int T1 = g_meta[3], T3 = g_meta[4];
    int q0 = tet[f * 4 + 0], q1 = tet[f * 4 + 1], q2 = tet[f * 4 + 2], q3 = tet[f * 4 + 3];
    int q[4] = {q0, q1, q2, q3};
    if (t == 15) {
        int row = T1 + 3 * T3 + g_innerX[f];
#pragma unroll
        for (int j = 0; j < 4; j++) g_allTets[row * 4 + j] = q[j];
        return;
    }
    int r = g_validX[f];
    if (c_NTET[t] == 1) {
        int row = g_ntt1X[f];
#pragma unroll
        for (int j = 0; j < 4; j++) {
            int e = c_TET[t][j];
            g_allTets[row * 4 + j] = (e < 4) ? q[e] : (g_idxmap[r * 6 + e - 4] + N);
        }
    } else {
        int row = T1 + 3 * g_ntt3X[f];
#pragma unroll
        for (int m = 0; m < 12; m++) {
            int e = c_TET[t][m];
            g_allTets[row * 4 + m] = (e < 4) ? q[e] : (g_idxmap[r * 6 + e - 4] + N);
        }
    }
}

__global__ void k_pmark() {
    int i = blockIdx.x * blockDim.x + threadIdx.x;
    if (i >= 4 * g_meta[9]) return;
    g_present[g_allTets[i]] = 1;
}

__global__ void k_meta2() {
    g_meta[11] = g_meta[10] + 3 * g_meta[7];
}

__global__ void k_vt(const float* pos, float* out, int N, int PL) {
    int idx = blockIdx.x * blockDim.x + threadIdx.x;
    if (idx >= PL) return;
    if (!g_present[idx]) return;
    int uid = g_presX[idx];
    float x, y, z;
    if (idx < N) {
        x = pos[idx * 3 + 0];
        y = pos[idx * 3 + 1];
        z = pos[idx * 3 + 2];
    } else {
        int e = idx - N;
        x = out[e * 3 + 0];
        y = out[e * 3 + 1];
        z = out[e * 3 + 2];
    }
    int o = g_meta[10];
    out[o + uid * 3 + 0] = x;
    out[o + uid * 3 + 1] = y;
    out[o + uid * 3 + 2] = z;
}

__global__ void k_tout(float* out) {
    int i = blockIdx.x * blockDim.x + threadIdx.x;
    if (i >= 4 * g_meta[9]) return;
    out[g_meta[11] + i] = (float)g_presX[g_allTets[i]];
}

// ---------------------------------------------------------------------------
// host launcher
// ---------------------------------------------------------------------------
static inline int gb(long long n) { return (int)((n + 255) / 256); }

static void run_scan(const int* in, int mode, int n, int* outPrefix, int* totalOut, int* bsums) {
    int nb = (n + 2047) / 2048;
    k_scan_partial<<<nb, 256>>>(in, mode, n, bsums);
    k_scan_single<<<1, 1024>>>(bsums, nb, totalOut);
    k_scan_final<<<nb, 256>>>(in, mode, n, bsums, outPrefix);
}

extern "C" void kernel_launch(void* const* d_in, const int* in_sizes, int n_in,
                              void* d_out, int out_size) {
    const float* pos = (const float*)d_in[0];
    const float* sdf = (const float*)d_in[1];
    const int* tet = (const int*)d_in[2];
    const float* thick = (const float*)d_in[3];
    float* out = (float*)d_out;

    int N = in_sizes[1];
    int F = in_sizes[2] / 4;
    if (N > MAXN) N = MAXN;
    if (F > MAXF) F = MAXF;
    int PL = N + MAXS;  // presence domain upper bound (tail stays zero)

    // device symbol addresses (runtime calls; not stream ops, capture-safe)
    int *p_ti, *p_validX, *p_nt1X, *p_nt2X, *p_ntt1X, *p_ntt3X, *p_innerX;
    int *p_bcnt, *p_bstart, *p_crossCnt, *p_crossX, *p_present, *p_presX, *p_bsums, *p_meta;
    cudaGetSymbolAddress((void**)&p_ti, g_ti);
    cudaGetSymbolAddress((void**)&p_validX, g_validX);
    cudaGetSymbolAddress((void**)&p_nt1X, g_nt1X);
    cudaGetSymbolAddress((void**)&p_nt2X, g_nt2X);
    cudaGetSymbolAddress((void**)&p_ntt1X, g_ntt1X);
    cudaGetSymbolAddress((void**)&p_ntt3X, g_ntt3X);
    cudaGetSymbolAddress((void**)&p_innerX, g_innerX);
    cudaGetSymbolAddress((void**)&p_bcnt, g_bcnt);
    cudaGetSymbolAddress((void**)&p_bstart, g_bstart);
    cudaGetSymbolAddress((void**)&p_crossCnt, g_crossCnt);
    cudaGetSymbolAddress((void**)&p_crossX, g_crossX);
    cudaGetSymbolAddress((void**)&p_present, g_present);
    cudaGetSymbolAddress((void**)&p_presX, g_presX);
    cudaGetSymbolAddress((void**)&p_bsums, g_bsums);
    cudaGetSymbolAddress((void**)&p_meta, g_meta);

    // 1. occupancy + per-tet pattern
    k_occ<<<gb(N), 256>>>(sdf, thick, N);
    k_ti<<<gb(F), 256>>>(tet, F);

    // 2. classification prefix sums over tets
    run_scan(p_ti, 0, F, p_validX, p_meta + 0, p_bsums);
    run_scan(p_ti, 1, F, p_nt1X, p_meta + 1, p_bsums);
    run_scan(p_ti, 2, F, p_nt2X, p_meta + 2, p_bsums);
    run_scan(p_ti, 3, F, p_ntt1X, p_meta + 3, p_bsums);
    run_scan(p_ti, 4, F, p_ntt3X, p_meta + 4, p_bsums);
    run_scan(p_ti, 5, F, p_innerX, p_meta + 5, p_bsums);

    // 3. edge bucketing by lo vertex (== lexicographic unique grouping)
    k_fill<<<gb(N), 256>>>(p_bcnt, 0, N);
    k_edge_count<<<gb(F), 256>>>(tet, F);
    run_scan(p_bcnt, -1, N, p_bstart, p_meta + 14, p_bsums);
    k_cur<<<gb(N), 256>>>(N);
    k_edge_scatter<<<gb(F), 256>>>(tet, F);

    // 4. per-bucket sort, dedupe, crossing-edge enumeration
    k_bsort<<<gb(N), 256>>>(N);
    run_scan(p_crossCnt, -1, N, p_crossX, p_meta + 6, p_bsums);
    k_bassign<<<gb(N), 256>>>(N);
    k_meta1<<<1, 1>>>();

    // 5. interpolated vertices (output region 0)
    k_verts<<<gb(MAXS), 256>>>(pos, sdf, thick, out);

    // 6. faces (output region 1)
    k_faces<<<gb(F), 256>>>(out, F);

    // 7. tetmesh connectivity build + presence unique
    k_tbuild<<<gb(F), 256>>>(tet, F, N);
    k_fill<<<gb(PL), 256>>>(p_present, 0, PL);
    k_pmark<<<gb(MAXTE), 256>>>();
    run_scan(p_present, -1, PL, p_presX, p_meta + 7, p_bsums);
    k_meta2<<<1, 1>>>();

    // 8. verts_tetmesh (region 2) + tets_tetmesh (region 3)
    k_vt<<<gb(PL), 256>>>(pos, out, N, PL);
    k_tout<<<gb(MAXTE), 256>>>(out);
}